// round 5
// baseline (speedup 1.0000x reference)
#include <cuda_runtime.h>

#define FULL 0xffffffffu

// ---------------------------------------------------------------------------
// Layout: ONE batch item per warp.
// Full 8-qubit state: 256 amps = 32 lanes x 8 local amps.
// Global amp index = (lane << 3) | j ; wire w<3 -> bit w of j (local),
// wire w>=3 -> bit (w-3) of lane.
// Product phase: psi_q simulated on lanes 0-15 while psi_k is simulated on
// lanes 16-31 simultaneously (same instructions, per-half parameters).
// ---------------------------------------------------------------------------

__device__ __forceinline__ float2 shfl2x(float2 v, int m) {
    v.x = __shfl_xor_sync(FULL, v.x, m);
    v.y = __shfl_xor_sync(FULL, v.y, m);
    return v;
}
__device__ __forceinline__ float2 shfl2s(float2 v, int src) {
    v.x = __shfl_sync(FULL, v.x, src);
    v.y = __shfl_sync(FULL, v.y, src);
    return v;
}
__device__ __forceinline__ float wred(float v) {  // full-warp sum
#pragma unroll
    for (int o = 16; o; o >>= 1) v += __shfl_xor_sync(FULL, v, o);
    return v;
}
__device__ __forceinline__ float hred(float v) {  // 16-lane group sum
#pragma unroll
    for (int o = 8; o; o >>= 1) v += __shfl_xor_sync(FULL, v, o);
    return v;
}

// a_new = c*a + (-i s)*o
__device__ __forceinline__ float2 rxmix(float2 a, float2 o, float c, float s) {
    return make_float2(c * a.x + s * o.y, c * a.y - s * o.x);
}

// general unitary [[u00,u01],[-conj(u01),conj(u00)]], own bit b
__device__ __forceinline__ float2 genmix(float2 x, float2 t, float4 u, int b) {
    float cx = u.x, cy = b ? -u.y : u.y;
    float dx = b ? -u.z : u.z, dy = u.w;
    return make_float2(cx * x.x - cy * x.y + dx * t.x - dy * t.y,
                       cx * x.y + cy * x.x + dx * t.y + dy * t.x);
}

// Distributed 16-amp register: 1 amp per lane within a 16-lane group
// (lg = lane & 15; xor shuffles with mask < 16 stay inside the group).
// |0000> -> (RX(xin) fused into rot L1) -> CRX ring -> IsingXX ring -> rot L2.
__device__ __forceinline__ float2 ring16(int lg, const float* xin,
                                         const float4* L1, const float4* L2,
                                         const float2* cs) {
    float2 v = make_float2(lg == 0 ? 1.f : 0.f, 0.f);
#pragma unroll
    for (int i = 0; i < 4; i++) {
        float s, c;
        __sincosf(0.5f * xin[i], &s, &c);
        float4 g = L1[i];
        float2 g00 = make_float2(g.x, g.y), g01 = make_float2(g.z, g.w);
        float2 u00 = rxmix(g00, g01, c, s);
        float2 u01 = rxmix(g01, g00, c, s);
        float4 u = make_float4(u00.x, u00.y, u01.x, u01.y);
        float2 t = shfl2x(v, 1 << i);
        v = genmix(v, t, u, (lg >> i) & 1);
    }
#pragma unroll
    for (int i = 0; i < 4; i++) {
        float2 t = shfl2x(v, 1 << ((i + 1) & 3));
        if ((lg >> i) & 1) v = rxmix(v, t, cs[i].x, cs[i].y);
    }
#pragma unroll
    for (int i = 0; i < 4; i++) {
        float2 t = shfl2x(v, (1 << i) | (1 << ((i + 1) & 3)));
        v = rxmix(v, t, cs[4 + i].x, cs[4 + i].y);
    }
#pragma unroll
    for (int i = 0; i < 4; i++) {
        float2 t = shfl2x(v, 1 << i);
        v = genmix(v, t, L2[i], (lg >> i) & 1);
    }
    return v;
}

// ---------------------------------------------------------------------------

__global__ void __launch_bounds__(64)
qa_fused(const float* __restrict__ x_text, const float* __restrict__ x_image,
         const float* __restrict__ W_text, const float* __restrict__ b_text,
         const float* __restrict__ W_image, const float* __restrict__ b_image,
         const float* __restrict__ qr, const float* __restrict__ qc,
         const float* __restrict__ kr, const float* __restrict__ kc,
         const float* __restrict__ vr, const float* __restrict__ vc,
         const float* __restrict__ cr, const float* __restrict__ cc,
         const float* __restrict__ cc2, const float* __restrict__ gates,
         float* __restrict__ out, int B, int IN) {
    // fused triples: [0..3] q L1, [4..7] q L2, [8..11] k L1, [12..15] k L2,
    //                [16..19] cross final, [20..23] v L1, [24..27] v L2
    __shared__ float4 sf[28];
    // cs: [0..7] q_crx, [8..15] k_crx, [16..23] c_crx, [24..31] c_crx2, [32..39] v_crx
    __shared__ float2 scs[40];

    for (int t = threadIdx.x; t < 68; t += blockDim.x) {
        if (t < 28) {
            int grp = t >> 2, i = t & 3;
            float a = 0.f, b = 0.f, c = 0.f;
            switch (grp) {
                case 0: a = qr[3 * i];      b = qr[3 * i + 1];      c = qr[3 * i + 2];      break;
                case 1: a = qr[12 + 3 * i]; b = qr[12 + 3 * i + 1]; c = qr[12 + 3 * i + 2]; break;
                case 2: a = kr[3 * i];      b = kr[3 * i + 1];      c = kr[3 * i + 2];      break;
                case 3: a = kr[12 + 3 * i]; b = kr[12 + 3 * i + 1]; c = kr[12 + 3 * i + 2]; break;
                case 4: a = cr[3 * i];      b = cr[3 * i + 1];      c = cr[3 * i + 2];      break;
                case 5: a = vr[3 * i];      b = vr[3 * i + 1];      c = vr[3 * i + 2];      break;
                case 6: a = vr[12 + 3 * i]; b = vr[12 + 3 * i + 1]; c = vr[12 + 3 * i + 2]; break;
            }
            float cb = cosf(0.5f * b), sb = sinf(0.5f * b);
            float sum = 0.5f * (a + c), dif = 0.5f * (a - c);
            sf[t] = make_float4(cb * cosf(sum), -cb * sinf(sum),
                                sb * sinf(dif), -sb * cosf(dif));
        } else {
            int u = t - 28;
            float p;
            if (u < 8) p = qc[u];
            else if (u < 16) p = kc[u - 8];
            else if (u < 24) p = cc[u - 16];
            else if (u < 32) p = cc2[u - 24];
            else p = vc[u - 32];
            float s, c;
            sincosf(0.5f * p, &s, &c);
            scs[u] = make_float2(c, s);
        }
    }
    __syncthreads();

    const int lane = threadIdx.x & 31;
    const int half = lane >> 4;   // 0: q-side, 1: k-side
    const int lg = lane & 15;
    const int item = (int)((blockIdx.x * blockDim.x + threadIdx.x) >> 5);
    const int itc = item < B ? item : (B - 1);

    // ---- projections: lower half computes xq rows, upper half xk rows ----
    float xin[4];
    {
        const float* xrow = (half ? x_image : x_text) + (long)itc * IN;
        const float* W = half ? W_image : W_text;
        const float* bb = half ? b_image : b_text;
#pragma unroll
        for (int r = 0; r < 4; r++) {
            float p = 0.f;
            for (int k = lg; k < IN; k += 16) p += xrow[k] * __ldg(&W[r * IN + k]);
            xin[r] = hred(p) + __ldg(&bb[r]);
        }
    }

    // ---- product phase: both 16-amp rings simultaneously ----
    const float4* sfb = sf + (half ? 8 : 0);
    const float2* csb = scs + (half ? 8 : 0);
    float2 ringv = ring16(lg, xin, sfb, sfb + 4, csb);

    // ---- assemble full 256-amp state ----
    // a[j] at global index (lane<<3)|j = psi_q[iq] * psi_k[ik]
    // iq = (j&7) | ((lane&1)<<3)  (psi_q on lanes 0..15)
    // ik = lane>>1               (psi_k on lanes 16..31)
    float2 kk = shfl2s(ringv, 16 + (lane >> 1));
    float2 a[8];
    {
        const int qb = (lane & 1) << 3;
#pragma unroll
        for (int j = 0; j < 8; j++) {
            float2 qj = shfl2s(ringv, j | qb);
            a[j] = make_float2(qj.x * kk.x - qj.y * kk.y,
                               qj.x * kk.y + qj.y * kk.x);
        }
    }

    // ---- cross entanglers ----
    // wire w<3 -> local bit w; wire w>=3 -> lane bit (w-3)
    // CRX(i, 4+i)
#pragma unroll
    for (int i = 0; i < 4; i++) {
        const float c = scs[16 + i].x, s = scs[16 + i].y;
        if (i < 3) {  // local ctrl, lane target (lane bit i+1)
#pragma unroll
            for (int j = 0; j < 8; j++)
                if ((j >> i) & 1) {
                    float2 t = shfl2x(a[j], 1 << (i + 1));
                    a[j] = rxmix(a[j], t, c, s);
                }
        } else {  // ctrl lane bit 0, target lane bit 4
            const int pred = lane & 1;
#pragma unroll
            for (int j = 0; j < 8; j++) {
                float2 t = shfl2x(a[j], 16);
                if (pred) a[j] = rxmix(a[j], t, c, s);
            }
        }
    }
    // CRX(4+i, i)
#pragma unroll
    for (int i = 0; i < 4; i++) {
        const float c = scs[20 + i].x, s = scs[20 + i].y;
        if (i < 3) {  // ctrl lane bit i+1, local target i
            if ((lane >> (i + 1)) & 1) {
                const int m = 1 << i;
#pragma unroll
                for (int j = 0; j < 8; j++)
                    if (!(j & m)) {
                        int j2 = j | m;
                        float2 x = a[j], p = a[j2];
                        a[j] = rxmix(x, p, c, s);
                        a[j2] = rxmix(p, x, c, s);
                    }
            }
        } else {  // ctrl lane bit 4, target lane bit 0
            const int pred = (lane >> 4) & 1;
#pragma unroll
            for (int j = 0; j < 8; j++) {
                float2 t = shfl2x(a[j], 1);
                if (pred) a[j] = rxmix(a[j], t, c, s);
            }
        }
    }
    // CRX2(i, ((i+1)&3)+4)
#pragma unroll
    for (int i = 0; i < 4; i++) {
        const float c = scs[24 + i].x, s = scs[24 + i].y;
        const int lm = 1 << (((i + 1) & 3) + 1);  // target lane mask
        if (i < 3) {
#pragma unroll
            for (int j = 0; j < 8; j++)
                if ((j >> i) & 1) {
                    float2 t = shfl2x(a[j], lm);
                    a[j] = rxmix(a[j], t, c, s);
                }
        } else {  // ctrl lane bit 0, target lane bit 1
            const int pred = lane & 1;
#pragma unroll
            for (int j = 0; j < 8; j++) {
                float2 t = shfl2x(a[j], 2);
                if (pred) a[j] = rxmix(a[j], t, c, s);
            }
        }
    }
    // CRX2(4+i, (i+1)&3)
#pragma unroll
    for (int i = 0; i < 4; i++) {
        const float c = scs[28 + i].x, s = scs[28 + i].y;
        const int tw = (i + 1) & 3;
        const int pred = (lane >> (i + 1)) & 1;
        if (tw < 3) {  // local target
            if (pred) {
                const int m = 1 << tw;
#pragma unroll
                for (int j = 0; j < 8; j++)
                    if (!(j & m)) {
                        int j2 = j | m;
                        float2 x = a[j], p = a[j2];
                        a[j] = rxmix(x, p, c, s);
                        a[j2] = rxmix(p, x, c, s);
                    }
            }
        } else {  // target wire 3 = lane bit 0 (i == 2)
#pragma unroll
            for (int j = 0; j < 8; j++) {
                float2 t = shfl2x(a[j], 1);
                if (pred) a[j] = rxmix(a[j], t, c, s);
            }
        }
    }
    // CNOT(i, 4+i) ; CNOT(4+i, i)
#pragma unroll
    for (int i = 0; i < 4; i++) {
        if (i < 3) {
#pragma unroll
            for (int j = 0; j < 8; j++)
                if ((j >> i) & 1) a[j] = shfl2x(a[j], 1 << (i + 1));
        } else {
            const int pred = lane & 1;
#pragma unroll
            for (int j = 0; j < 8; j++) {
                float2 t = shfl2x(a[j], 16);
                if (pred) a[j] = t;
            }
        }
        if (i < 3) {
            if ((lane >> (i + 1)) & 1) {
                const int m = 1 << i;
#pragma unroll
                for (int j = 0; j < 8; j++)
                    if (!(j & m)) {
                        int j2 = j | m;
                        float2 t = a[j];
                        a[j] = a[j2];
                        a[j2] = t;
                    }
            }
        } else {
            const int pred = (lane >> 4) & 1;
#pragma unroll
            for (int j = 0; j < 8; j++) {
                float2 t = shfl2x(a[j], 1);
                if (pred) a[j] = t;
            }
        }
    }
    // final rot layer (wires 0..3)
#pragma unroll
    for (int i = 0; i < 4; i++) {
        float4 u = sf[16 + i];
        if (i < 3) {
            const int m = 1 << i;
#pragma unroll
            for (int j = 0; j < 8; j++)
                if (!(j & m)) {
                    int j2 = j | m;
                    float2 x = a[j], p = a[j2];
                    a[j] = make_float2(u.x * x.x - u.y * x.y + u.z * p.x - u.w * p.y,
                                       u.x * x.y + u.y * x.x + u.z * p.y + u.w * p.x);
                    a[j2] = make_float2(u.x * p.x + u.y * p.y - u.z * x.x - u.w * x.y,
                                        u.x * p.y - u.y * p.x - u.z * x.y + u.w * x.x);
                }
        } else {
            const int b = lane & 1;
#pragma unroll
            for (int j = 0; j < 8; j++) {
                float2 t = shfl2x(a[j], 1);
                a[j] = genmix(a[j], t, u, b);
            }
        }
    }

    // ---- measurements -> amp4 ----
    float amp4[4];
#pragma unroll
    for (int w = 0; w < 4; w++) {
        float z = 0.f, x = 0.f;
        if (w < 3) {
            const int m = 1 << w;
#pragma unroll
            for (int j = 0; j < 8; j++) {
                float n = a[j].x * a[j].x + a[j].y * a[j].y;
                z += (j & m) ? -n : n;
                float2 o = a[j ^ m];
                x += a[j].x * o.x + a[j].y * o.y;
            }
        } else {
            const float sgn = (lane & 1) ? -1.f : 1.f;
#pragma unroll
            for (int j = 0; j < 8; j++) {
                float n = a[j].x * a[j].x + a[j].y * a[j].y;
                z += sgn * n;
                float2 o = shfl2x(a[j], 1);
                x += a[j].x * o.x + a[j].y * o.y;
            }
        }
        z = wred(z);
        x = wred(x);
        amp4[w] = sqrtf(z * z + x * x);
    }

    // ---- value circuit: replicated in both 16-lane halves ----
    float xkv[4];
#pragma unroll
    for (int i = 0; i < 4; i++) xkv[i] = __shfl_sync(FULL, xin[i], 16);

    float2 v = ring16(lg, xkv, sf + 20, sf + 24, scs + 32);
#pragma unroll
    for (int i = 0; i < 4; i++) {
        float ang = tanhf(amp4[i]) * __ldg(&gates[i]);
        float s, c;
        __sincosf(0.5f * ang, &s, &c);
        float2 t = shfl2x(v, 1 << i);
        v = rxmix(v, t, c, s);
    }
#pragma unroll
    for (int i = 0; i < 4; i++) {
        float2 t = shfl2x(v, 1 << ((i + 1) & 3));
        if ((lg >> i) & 1) v = t;
    }

    // ---- measure + store ----
    float zres[4], xres[4];
#pragma unroll
    for (int w = 0; w < 4; w++) {
        float n = v.x * v.x + v.y * v.y;
        zres[w] = hred(((lg >> w) & 1) ? -n : n);
        float2 t = shfl2x(v, 1 << w);
        xres[w] = hred(v.x * t.x + v.y * t.y);
    }
    if (lane == 0 && item < B) {
        float4* o0 = (float4*)(out + (long)item * 8);
        o0[0] = make_float4(zres[0], zres[1], zres[2], zres[3]);
        o0[1] = make_float4(xres[0], xres[1], xres[2], xres[3]);
    }
}

// ---------------------------------------------------------------------------

extern "C" void kernel_launch(void* const* d_in, const int* in_sizes, int n_in,
                              void* d_out, int out_size) {
    const float* x_text  = (const float*)d_in[0];
    const float* x_image = (const float*)d_in[1];
    const float* W_text  = (const float*)d_in[2];
    const float* b_text  = (const float*)d_in[3];
    const float* W_image = (const float*)d_in[4];
    const float* b_image = (const float*)d_in[5];
    const float* q_rot   = (const float*)d_in[6];
    const float* q_crx   = (const float*)d_in[7];
    const float* k_rot   = (const float*)d_in[8];
    const float* k_crx   = (const float*)d_in[9];
    const float* v_rot   = (const float*)d_in[10];
    const float* v_crx   = (const float*)d_in[11];
    const float* c_rot   = (const float*)d_in[12];
    const float* c_crx   = (const float*)d_in[13];
    const float* c_crx2  = (const float*)d_in[14];
    const float* gates   = (const float*)d_in[15];

    int IN = in_sizes[2] / 4;   // W_text is [4, IN]
    int B  = in_sizes[0] / IN;  // x_text is [B, IN]

    int threads = 64;           // 2 warps per block, 1 item per warp
    int blocks = (B * 32 + threads - 1) / threads;
    qa_fused<<<blocks, threads>>>(x_text, x_image, W_text, b_text, W_image, b_image,
                                  q_rot, q_crx, k_rot, k_crx, v_rot, v_crx,
                                  c_rot, c_crx, c_crx2, gates,
                                  (float*)d_out, B, IN);
}

// round 6
// speedup vs baseline: 1.1325x; 1.1325x over previous
#include <cuda_runtime.h>

#define FULL 0xffffffffu

// ---------------------------------------------------------------------------
// Layout (R4): half-warp (16 lanes) per batch item, 2 items per warp.
// Full 8-qubit state: 256 amps = 16 lanes x 16 local amps.
// Global amp index = (lg << 4) | j ; wire w<4 -> bit w of j (local),
// wire w>=4 -> bit (w-4) of lg (lane).
// Product phase: psi_q, psi_k, and the value register are three independent
// distributed 16-amp states (1 amp/lane) advanced in ONE interleaved loop
// (ILP=3) to hide shuffle latency.
// ---------------------------------------------------------------------------

__device__ __forceinline__ float2 shfl2x(float2 v, int m) {
    v.x = __shfl_xor_sync(FULL, v.x, m);
    v.y = __shfl_xor_sync(FULL, v.y, m);
    return v;
}
__device__ __forceinline__ float2 shfl2i(float2 v, int src) {  // within 16-group
    v.x = __shfl_sync(FULL, v.x, src, 16);
    v.y = __shfl_sync(FULL, v.y, src, 16);
    return v;
}
__device__ __forceinline__ float hred(float v) {  // 16-lane group sum
#pragma unroll
    for (int o = 8; o; o >>= 1) v += __shfl_xor_sync(FULL, v, o);
    return v;
}

// a_new = c*a + (-i s)*o
__device__ __forceinline__ float2 rxmix(float2 a, float2 o, float c, float s) {
    return make_float2(c * a.x + s * o.y, c * a.y - s * o.x);
}

// general unitary [[u00,u01],[-conj(u01),conj(u00)]], own bit b
__device__ __forceinline__ float2 genmix(float2 x, float2 t, float4 u, int b) {
    float cx = u.x, cy = b ? -u.y : u.y;
    float dx = b ? -u.z : u.z, dy = u.w;
    return make_float2(cx * x.x - cy * x.y + dx * t.x - dy * t.y,
                       cx * x.y + cy * x.x + dx * t.y + dy * t.x);
}

// fuse a data-dependent RX into a constant GEN triple: U = GEN @ RX(theta)
__device__ __forceinline__ float4 fuse_rx(float4 g, float c, float s) {
    float2 g00 = make_float2(g.x, g.y), g01 = make_float2(g.z, g.w);
    float2 u00 = rxmix(g00, g01, c, s);
    float2 u01 = rxmix(g01, g00, c, s);
    return make_float4(u00.x, u00.y, u01.x, u01.y);
}

// ---------------------------------------------------------------------------

__global__ void __launch_bounds__(64, 1)
qa_fused(const float* __restrict__ x_text, const float* __restrict__ x_image,
         const float* __restrict__ W_text, const float* __restrict__ b_text,
         const float* __restrict__ W_image, const float* __restrict__ b_image,
         const float* __restrict__ qr, const float* __restrict__ qc,
         const float* __restrict__ kr, const float* __restrict__ kc,
         const float* __restrict__ vr, const float* __restrict__ vc,
         const float* __restrict__ cr, const float* __restrict__ cc,
         const float* __restrict__ cc2, const float* __restrict__ gates,
         float* __restrict__ out, int B, int IN) {
    // fused triples: [0..3] q L1, [4..7] q L2, [8..11] k L1, [12..15] k L2,
    //                [16..19] cross final, [20..23] v L1, [24..27] v L2
    __shared__ float4 sf[28];
    // cs: [0..7] q_crx, [8..15] k_crx, [16..23] c_crx, [24..31] c_crx2, [32..39] v_crx
    __shared__ float2 scs[40];
    __shared__ float sgates[4];

    for (int t = threadIdx.x; t < 72; t += blockDim.x) {
        if (t < 28) {
            int grp = t >> 2, i = t & 3;
            float a = 0.f, b = 0.f, c = 0.f;
            switch (grp) {
                case 0: a = qr[3 * i];      b = qr[3 * i + 1];      c = qr[3 * i + 2];      break;
                case 1: a = qr[12 + 3 * i]; b = qr[12 + 3 * i + 1]; c = qr[12 + 3 * i + 2]; break;
                case 2: a = kr[3 * i];      b = kr[3 * i + 1];      c = kr[3 * i + 2];      break;
                case 3: a = kr[12 + 3 * i]; b = kr[12 + 3 * i + 1]; c = kr[12 + 3 * i + 2]; break;
                case 4: a = cr[3 * i];      b = cr[3 * i + 1];      c = cr[3 * i + 2];      break;
                case 5: a = vr[3 * i];      b = vr[3 * i + 1];      c = vr[3 * i + 2];      break;
                case 6: a = vr[12 + 3 * i]; b = vr[12 + 3 * i + 1]; c = vr[12 + 3 * i + 2]; break;
            }
            float cb = cosf(0.5f * b), sb = sinf(0.5f * b);
            float sum = 0.5f * (a + c), dif = 0.5f * (a - c);
            sf[t] = make_float4(cb * cosf(sum), -cb * sinf(sum),
                                sb * sinf(dif), -sb * cosf(dif));
        } else if (t < 68) {
            int u = t - 28;
            float p;
            if (u < 8) p = qc[u];
            else if (u < 16) p = kc[u - 8];
            else if (u < 24) p = cc[u - 16];
            else if (u < 32) p = cc2[u - 24];
            else p = vc[u - 32];
            float s, c;
            sincosf(0.5f * p, &s, &c);
            scs[u] = make_float2(c, s);
        } else {
            sgates[t - 68] = gates[t - 68];
        }
    }
    __syncthreads();

    const int lane = threadIdx.x & 31;
    const int half = lane >> 4;
    const int lg = lane & 15;
    const int gw = (int)((blockIdx.x * blockDim.x + threadIdx.x) >> 5);
    const int item = gw * 2 + half;
    const int itc = item < B ? item : (B - 1);

    // ---- projections ----
    float xq[4], xk[4];
    {
        const float* xt = x_text + (long)itc * IN;
        const float* xi = x_image + (long)itc * IN;
#pragma unroll
        for (int r = 0; r < 4; r++) {
            float pq = 0.f, pk = 0.f;
            for (int k = lg; k < IN; k += 16) {
                pq += xt[k] * __ldg(&W_text[r * IN + k]);
                pk += xi[k] * __ldg(&W_image[r * IN + k]);
            }
            xq[r] = hred(pq) + __ldg(&b_text[r]);
            xk[r] = hred(pk) + __ldg(&b_image[r]);
        }
    }

    // ---- product phase: THREE independent 16-amp rings, interleaved (ILP=3) ----
    float2 vq = make_float2(lg == 0 ? 1.f : 0.f, 0.f);
    float2 vk = vq, vv = vq;

    // L1 rot layers with fused data-dependent RX embeddings
#pragma unroll
    for (int i = 0; i < 4; i++) {
        float sq, cq, sk, ck;
        __sincosf(0.5f * xq[i], &sq, &cq);
        __sincosf(0.5f * xk[i], &sk, &ck);
        float4 uq = fuse_rx(sf[i], cq, sq);
        float4 uk = fuse_rx(sf[8 + i], ck, sk);
        float4 uv = fuse_rx(sf[20 + i], ck, sk);
        const int b = (lg >> i) & 1;
        float2 tq = shfl2x(vq, 1 << i);
        float2 tk = shfl2x(vk, 1 << i);
        float2 tv = shfl2x(vv, 1 << i);
        vq = genmix(vq, tq, uq, b);
        vk = genmix(vk, tk, uk, b);
        vv = genmix(vv, tv, uv, b);
    }
    // CRX rings
#pragma unroll
    for (int i = 0; i < 4; i++) {
        const int m = 1 << ((i + 1) & 3);
        const int p = (lg >> i) & 1;
        float2 tq = shfl2x(vq, m);
        float2 tk = shfl2x(vk, m);
        float2 tv = shfl2x(vv, m);
        if (p) {
            vq = rxmix(vq, tq, scs[i].x, scs[i].y);
            vk = rxmix(vk, tk, scs[8 + i].x, scs[8 + i].y);
            vv = rxmix(vv, tv, scs[32 + i].x, scs[32 + i].y);
        }
    }
    // IsingXX rings
#pragma unroll
    for (int i = 0; i < 4; i++) {
        const int m = (1 << i) | (1 << ((i + 1) & 3));
        float2 tq = shfl2x(vq, m);
        float2 tk = shfl2x(vk, m);
        float2 tv = shfl2x(vv, m);
        vq = rxmix(vq, tq, scs[4 + i].x, scs[4 + i].y);
        vk = rxmix(vk, tk, scs[12 + i].x, scs[12 + i].y);
        vv = rxmix(vv, tv, scs[36 + i].x, scs[36 + i].y);
    }
    // L2 rot layers
#pragma unroll
    for (int i = 0; i < 4; i++) {
        const int b = (lg >> i) & 1;
        float2 tq = shfl2x(vq, 1 << i);
        float2 tk = shfl2x(vk, 1 << i);
        float2 tv = shfl2x(vv, 1 << i);
        vq = genmix(vq, tq, sf[4 + i], b);
        vk = genmix(vk, tk, sf[12 + i], b);
        vv = genmix(vv, tv, sf[24 + i], b);
    }

    // ---- assemble full 256-amp state: a[j] = psi_q[j] * psi_k[lg] ----
    float2 a[16];
#pragma unroll
    for (int j = 0; j < 16; j++) {
        float2 qj = shfl2i(vq, j);
        a[j] = make_float2(qj.x * vk.x - qj.y * vk.y,
                           qj.x * vk.y + qj.y * vk.x);
    }

    // ---- cross entanglers (wires 0..3 local bits of j, wires 4..7 bits of lg) ----
    // CRX(i, 4+i): local ctrl, lane target
#pragma unroll
    for (int i = 0; i < 4; i++) {
        const float c = scs[16 + i].x, s = scs[16 + i].y;
        const int ml = 1 << i;
#pragma unroll
        for (int j = 0; j < 16; j++)
            if ((j >> i) & 1) {
                float2 t = shfl2x(a[j], ml);
                a[j] = rxmix(a[j], t, c, s);
            }
    }
    // CRX(4+i, i): lane ctrl, local target (no shuffles)
#pragma unroll
    for (int i = 0; i < 4; i++) {
        const float c = scs[20 + i].x, s = scs[20 + i].y;
        if ((lg >> i) & 1) {
            const int m = 1 << i;
#pragma unroll
            for (int j = 0; j < 16; j++)
                if (!(j & m)) {
                    int j2 = j | m;
                    float2 x = a[j], p = a[j2];
                    a[j] = rxmix(x, p, c, s);
                    a[j2] = rxmix(p, x, c, s);
                }
        }
    }
    // CRX2(i, ((i+1)&3)+4)
#pragma unroll
    for (int i = 0; i < 4; i++) {
        const float c = scs[24 + i].x, s = scs[24 + i].y;
        const int ml = 1 << ((i + 1) & 3);
#pragma unroll
        for (int j = 0; j < 16; j++)
            if ((j >> i) & 1) {
                float2 t = shfl2x(a[j], ml);
                a[j] = rxmix(a[j], t, c, s);
            }
    }
    // CRX2(4+i, (i+1)&3)
#pragma unroll
    for (int i = 0; i < 4; i++) {
        const float c = scs[28 + i].x, s = scs[28 + i].y;
        if ((lg >> i) & 1) {
            const int m = 1 << ((i + 1) & 3);
#pragma unroll
            for (int j = 0; j < 16; j++)
                if (!(j & m)) {
                    int j2 = j | m;
                    float2 x = a[j], p = a[j2];
                    a[j] = rxmix(x, p, c, s);
                    a[j2] = rxmix(p, x, c, s);
                }
        }
    }
    // CNOT(i, 4+i) then CNOT(4+i, i)
#pragma unroll
    for (int i = 0; i < 4; i++) {
        const int ml = 1 << i;
#pragma unroll
        for (int j = 0; j < 16; j++)
            if ((j >> i) & 1) a[j] = shfl2x(a[j], ml);
        if ((lg >> i) & 1) {
            const int m = 1 << i;
#pragma unroll
            for (int j = 0; j < 16; j++)
                if (!(j & m)) {
                    int j2 = j | m;
                    float2 t = a[j];
                    a[j] = a[j2];
                    a[j2] = t;
                }
        }
    }
    // final rot layer (wires 0..3, local, no shuffles)
#pragma unroll
    for (int i = 0; i < 4; i++) {
        float4 u = sf[16 + i];
        const int m = 1 << i;
#pragma unroll
        for (int j = 0; j < 16; j++)
            if (!(j & m)) {
                int j2 = j | m;
                float2 x = a[j], p = a[j2];
                a[j] = make_float2(u.x * x.x - u.y * x.y + u.z * p.x - u.w * p.y,
                                   u.x * x.y + u.y * x.x + u.z * p.y + u.w * p.x);
                a[j2] = make_float2(u.x * p.x + u.y * p.y - u.z * x.x - u.w * x.y,
                                    u.x * p.y - u.y * p.x - u.z * x.y + u.w * x.x);
            }
    }

    // ---- measurements -> amp4 (wires 0..3 local: register gathers only) ----
    float amp4[4];
#pragma unroll
    for (int w = 0; w < 4; w++) {
        const int m = 1 << w;
        float z = 0.f, x = 0.f;
#pragma unroll
        for (int j = 0; j < 16; j++) {
            float n = a[j].x * a[j].x + a[j].y * a[j].y;
            z += (j & m) ? -n : n;
            float2 o = a[j ^ m];
            x += a[j].x * o.x + a[j].y * o.y;
        }
        z = hred(z);
        x = hred(x);
        amp4[w] = sqrtf(z * z + x * x);
    }

    // ---- value circuit tail on vv ----
#pragma unroll
    for (int i = 0; i < 4; i++) {
        float ang = tanhf(amp4[i]) * sgates[i];
        float s, c;
        __sincosf(0.5f * ang, &s, &c);
        float2 t = shfl2x(vv, 1 << i);
        vv = rxmix(vv, t, c, s);
    }
#pragma unroll
    for (int i = 0; i < 4; i++) {
        float2 t = shfl2x(vv, 1 << ((i + 1) & 3));
        if ((lg >> i) & 1) vv = t;
    }

    // ---- measure + store ----
    float zres[4], xres[4];
#pragma unroll
    for (int w = 0; w < 4; w++) {
        float n = vv.x * vv.x + vv.y * vv.y;
        zres[w] = hred(((lg >> w) & 1) ? -n : n);
        float2 t = shfl2x(vv, 1 << w);
        xres[w] = hred(vv.x * t.x + vv.y * t.y);
    }
    if (lg == 0 && item < B) {
        float4* o0 = (float4*)(out + (long)item * 8);
        o0[0] = make_float4(zres[0], zres[1], zres[2], zres[3]);
        o0[1] = make_float4(xres[0], xres[1], xres[2], xres[3]);
    }
}

// ---------------------------------------------------------------------------

extern "C" void kernel_launch(void* const* d_in, const int* in_sizes, int n_in,
                              void* d_out, int out_size) {
    const float* x_text  = (const float*)d_in[0];
    const float* x_image = (const float*)d_in[1];
    const float* W_text  = (const float*)d_in[2];
    const float* b_text  = (const float*)d_in[3];
    const float* W_image = (const float*)d_in[4];
    const float* b_image = (const float*)d_in[5];
    const float* q_rot   = (const float*)d_in[6];
    const float* q_crx   = (const float*)d_in[7];
    const float* k_rot   = (const float*)d_in[8];
    const float* k_crx   = (const float*)d_in[9];
    const float* v_rot   = (const float*)d_in[10];
    const float* v_crx   = (const float*)d_in[11];
    const float* c_rot   = (const float*)d_in[12];
    const float* c_crx   = (const float*)d_in[13];
    const float* c_crx2  = (const float*)d_in[14];
    const float* gates   = (const float*)d_in[15];

    int IN = in_sizes[2] / 4;   // W_text is [4, IN]
    int B  = in_sizes[0] / IN;  // x_text is [B, IN]

    int nwarps = (B + 1) / 2;   // 2 items per warp
    int threads = 64;
    int blocks = (nwarps * 32 + threads - 1) / threads;
    qa_fused<<<blocks, threads>>>(x_text, x_image, W_text, b_text, W_image, b_image,
                                  q_rot, q_crx, k_rot, k_crx, v_rot, v_crx,
                                  c_rot, c_crx, c_crx2, gates,
                                  (float*)d_out, B, IN);
}